// round 3
// baseline (speedup 1.0000x reference)
#include <cuda_runtime.h>
#include <cstdint>

#define NN 32768
#define TT 16
#define FF 256
#define HH 16
#define DD 16
#define MM (NN*TT)     // 524288 rows

// -------- scratch (alloc-guard-safe __device__ globals) --------
// g_q is reused as ctx by the attention kernel (per-node reads finish
// before the per-node writes inside one CTA, so aliasing is safe).
__device__ float g_q[134217728];   // 512 MB  (q, then ctx)
__device__ float g_k[134217728];   // 512 MB
__device__ float g_v[134217728];   // 512 MB

// -------- GEMM config --------
#define BM 128
#define BN 128
#define BK 32
#define AS_STRIDE 36    // [BM][36]
#define BS_STRIDE 132   // [BK][132] and Ys [BM][132]

__device__ __forceinline__ uint32_t ftf32(float x) {
    uint32_t r;
    asm("cvt.rna.tf32.f32 %0, %1;" : "=r"(r) : "f"(x));
    return r;
}

__device__ __forceinline__ void mma_tf32(float c[4],
                                         uint32_t a0, uint32_t a1, uint32_t a2, uint32_t a3,
                                         uint32_t b0, uint32_t b1) {
    asm volatile(
        "mma.sync.aligned.m16n8k8.row.col.f32.tf32.tf32.f32 "
        "{%0,%1,%2,%3},{%4,%5,%6,%7},{%8,%9},{%0,%1,%2,%3};"
        : "+f"(c[0]), "+f"(c[1]), "+f"(c[2]), "+f"(c[3])
        : "r"(a0), "r"(a1), "r"(a2), "r"(a3), "r"(b0), "r"(b1));
}

// One GEMM kernel, two modes:
//   mode 0: C = op(A(+pos)) @ B            -> store fp32 to Cout
//   mode 1: ff epilogue: y = relu(acc + bias) + ctx + resid + pos, then
//           mean over T (16 consecutive rows) -> outmean[node, col]
// btrans: 0 -> B is [K,N] row-major (Wq/Wk/Wv); 1 -> B is [N,K] row-major (lin_w)
__global__ void gemm_k(const float* __restrict__ A,
                       const float* __restrict__ pos, int addpos,
                       const float* __restrict__ B, int btrans,
                       float* __restrict__ Cout, int mode,
                       const float* __restrict__ ctxp,
                       const float* __restrict__ resid,
                       const float* __restrict__ bias,
                       float* __restrict__ outmean) {
    extern __shared__ float sh[];
    float* As = sh;                       // [128][36]  = 4608 floats
    float* Bs = sh + BM * AS_STRIDE;      // [32][132]  = 4224 floats
    float* Ys = sh;                       // [128][132] = 16896 floats (aliases As/Bs; used after final sync)

    const int tid  = threadIdx.x;
    const int lane = tid & 31;
    const int warp = tid >> 5;
    const int wm   = warp & 3;            // 4 warps along M (32 rows each)
    const int wn   = warp >> 2;           // 2 warps along N (64 cols each)
    const int tile_n = blockIdx.x;
    const int tile_m = blockIdx.y;
    const size_t row0 = (size_t)tile_m * BM;
    const int col0 = tile_n * BN;

    float acc[2][8][4];
#pragma unroll
    for (int mt = 0; mt < 2; mt++)
#pragma unroll
        for (int nt = 0; nt < 8; nt++)
#pragma unroll
            for (int e = 0; e < 4; e++) acc[mt][nt][e] = 0.f;

    for (int kb = 0; kb < FF; kb += BK) {
        // ---- load A tile [128 x 32] (1024 float4) ----
#pragma unroll
        for (int q = 0; q < 4; q++) {
            int idx = tid + q * 256;          // 0..1023
            int r = idx >> 3;                 // 0..127
            int c = (idx & 7) * 4;            // 0..28
            float4 t = *(const float4*)(A + (row0 + r) * FF + kb + c);
            if (addpos) {
                float4 p = *(const float4*)(pos + (r & 15) * FF + kb + c);
                t.x += p.x; t.y += p.y; t.z += p.z; t.w += p.w;
            }
            float* dst = As + r * AS_STRIDE + c;
            dst[0] = __uint_as_float(ftf32(t.x));
            dst[1] = __uint_as_float(ftf32(t.y));
            dst[2] = __uint_as_float(ftf32(t.z));
            dst[3] = __uint_as_float(ftf32(t.w));
        }
        // ---- load B tile [32 x 128] ----
        if (!btrans) {
#pragma unroll
            for (int q = 0; q < 4; q++) {
                int idx = tid + q * 256;
                int r = idx >> 5;             // 0..31 (k)
                int c = (idx & 31) * 4;       // 0..124 (n)
                float4 t = *(const float4*)(B + (size_t)(kb + r) * FF + col0 + c);
                float* dst = Bs + r * BS_STRIDE + c;
                dst[0] = __uint_as_float(ftf32(t.x));
                dst[1] = __uint_as_float(ftf32(t.y));
                dst[2] = __uint_as_float(ftf32(t.z));
                dst[3] = __uint_as_float(ftf32(t.w));
            }
        } else {
#pragma unroll
            for (int q = 0; q < 4; q++) {
                int idx = tid + q * 256;
                int nloc = idx >> 3;          // 0..127
                int k = (idx & 7) * 4;        // 0..28
                float4 t = *(const float4*)(B + (size_t)(col0 + nloc) * FF + kb + k);
                Bs[(k + 0) * BS_STRIDE + nloc] = __uint_as_float(ftf32(t.x));
                Bs[(k + 1) * BS_STRIDE + nloc] = __uint_as_float(ftf32(t.y));
                Bs[(k + 2) * BS_STRIDE + nloc] = __uint_as_float(ftf32(t.z));
                Bs[(k + 3) * BS_STRIDE + nloc] = __uint_as_float(ftf32(t.w));
            }
        }
        __syncthreads();

        // ---- compute: 4 k-steps of 8 ----
#pragma unroll
        for (int kk = 0; kk < 4; kk++) {
            uint32_t af[2][4], bf[8][2];
#pragma unroll
            for (int mt = 0; mt < 2; mt++) {
                int r = wm * 32 + mt * 16 + (lane >> 2);
                int c = kk * 8 + (lane & 3);
                af[mt][0] = __float_as_uint(As[r * AS_STRIDE + c]);
                af[mt][1] = __float_as_uint(As[(r + 8) * AS_STRIDE + c]);
                af[mt][2] = __float_as_uint(As[r * AS_STRIDE + c + 4]);
                af[mt][3] = __float_as_uint(As[(r + 8) * AS_STRIDE + c + 4]);
            }
#pragma unroll
            for (int nt = 0; nt < 8; nt++) {
                int cn = wn * 64 + nt * 8 + (lane >> 2);
                int rk = kk * 8 + (lane & 3);
                bf[nt][0] = __float_as_uint(Bs[rk * BS_STRIDE + cn]);
                bf[nt][1] = __float_as_uint(Bs[(rk + 4) * BS_STRIDE + cn]);
            }
#pragma unroll
            for (int mt = 0; mt < 2; mt++)
#pragma unroll
                for (int nt = 0; nt < 8; nt++)
                    mma_tf32(acc[mt][nt], af[mt][0], af[mt][1], af[mt][2], af[mt][3],
                             bf[nt][0], bf[nt][1]);
        }
        __syncthreads();
    }

    if (mode == 0) {
#pragma unroll
        for (int mt = 0; mt < 2; mt++)
#pragma unroll
            for (int nt = 0; nt < 8; nt++) {
                int r = wm * 32 + mt * 16 + (lane >> 2);
                int c = wn * 64 + nt * 8 + (lane & 3) * 2;
                float2* p0 = (float2*)(Cout + (row0 + r) * FF + col0 + c);
                *p0 = make_float2(acc[mt][nt][0], acc[mt][nt][1]);
                float2* p1 = (float2*)(Cout + (row0 + r + 8) * FF + col0 + c);
                *p1 = make_float2(acc[mt][nt][2], acc[mt][nt][3]);
            }
    } else {
        // ff epilogue: y = relu(acc+bias) + ctx + inputs + pos, stage in Ys
#pragma unroll
        for (int mt = 0; mt < 2; mt++)
#pragma unroll
            for (int nt = 0; nt < 8; nt++) {
                int lr = wm * 32 + mt * 16 + (lane >> 2);
                int lc = wn * 64 + nt * 8 + (lane & 3) * 2;
#pragma unroll
                for (int half = 0; half < 2; half++) {
                    int rr = lr + half * 8;
                    size_t gm = row0 + rr;
#pragma unroll
                    for (int cc = 0; cc < 2; cc++) {
                        int col = lc + cc;
                        float v = acc[mt][nt][half * 2 + cc] + bias[col0 + col];
                        v = fmaxf(v, 0.f);
                        size_t gi = gm * FF + col0 + col;
                        v += ctxp[gi] + resid[gi] + pos[(rr & 15) * FF + col0 + col];
                        Ys[rr * BS_STRIDE + col] = v;
                    }
                }
            }
        __syncthreads();
        // mean over T: tile covers exactly 8 nodes (128 rows)
#pragma unroll
        for (int rep = 0; rep < 4; rep++) {
            int o = rep * 256 + tid;          // 0..1023 = 8 nodes x 128 cols
            int node = o >> 7;
            int c = o & 127;
            float s = 0.f;
#pragma unroll
            for (int t2 = 0; t2 < 16; t2++) s += Ys[(node * 16 + t2) * BS_STRIDE + c];
            outmean[((size_t)tile_m * 8 + node) * FF + col0 + c] = s * (1.f / 16.f);
        }
    }
}

// -------- attention: 1 CTA per node, 1 thread per (query i, head h) --------
#define QS 260   // padded row stride (floats)

__global__ void attn_k(float* __restrict__ ST) {
    extern __shared__ float sh[];
    float* qs = sh;                // [16][260]
    float* ks = sh + 16 * QS;
    float* vs = sh + 32 * QS;

    const int n = blockIdx.x;
    const int tid = threadIdx.x;
    const size_t base = (size_t)n * (TT * FF);   // 4096

    // load q,k,v tiles [16 x 256] each (float4, 2-way-conflict sts acceptable)
#pragma unroll
    for (int r = 0; r < 4; r++) {
        int idx = tid + r * 256;        // float4 index 0..1023
        int row = idx >> 6;
        int col = (idx & 63) * 4;
        *(float4*)(qs + row * QS + col) = *(const float4*)(g_q + base + row * FF + col);
        *(float4*)(ks + row * QS + col) = *(const float4*)(g_k + base + row * FF + col);
        *(float4*)(vs + row * QS + col) = *(const float4*)(g_v + base + row * FF + col);
    }
    __syncthreads();

    const int i = tid & 15;     // query row
    const int h = tid >> 4;     // head
    const float* qrow = qs + i * QS + h * 16;

    float qr[16];
#pragma unroll
    for (int d = 0; d < 16; d++) qr[d] = qrow[d];

    float sc[16];
    float mx = -1e30f;
#pragma unroll
    for (int j = 0; j < 16; j++) {
        const float* kr = ks + j * QS + h * 16;
        float s = 0.f;
#pragma unroll
        for (int d = 0; d < 16; d++) s += qr[d] * kr[d];
        s *= 0.25f;                     // 1/sqrt(T), T=16
        sc[j] = s;
        mx = fmaxf(mx, s);
    }
    float sum = 0.f;
#pragma unroll
    for (int j = 0; j < 16; j++) { sc[j] = __expf(sc[j] - mx); sum += sc[j]; }
    float inv = 1.f / sum;
    float at[16];
#pragma unroll
    for (int j = 0; j < 16; j++) at[j] = sc[j] * inv;

    // ST[n, i, h*16 + j]
    float* stp = ST + base + i * FF + h * 16;
#pragma unroll
    for (int j0 = 0; j0 < 16; j0 += 4)
        *(float4*)(stp + j0) = make_float4(at[j0], at[j0 + 1], at[j0 + 2], at[j0 + 3]);

    // ctx[n, i, h*16 + d] = sum_j at[j] * v[j, h*16+d]  -> overwrite g_q (safe: reads done)
    float* cp = g_q + base + i * FF + h * 16;
#pragma unroll
    for (int d0 = 0; d0 < 16; d0 += 4) {
        float o[4] = {0.f, 0.f, 0.f, 0.f};
#pragma unroll
        for (int j = 0; j < 16; j++) {
            const float* vr = vs + j * QS + h * 16 + d0;
            o[0] += at[j] * vr[0];
            o[1] += at[j] * vr[1];
            o[2] += at[j] * vr[2];
            o[3] += at[j] * vr[3];
        }
        *(float4*)(cp + d0) = make_float4(o[0], o[1], o[2], o[3]);
    }
}

extern "C" void kernel_launch(void* const* d_in, const int* in_sizes, int n_in,
                              void* d_out, int out_size) {
    (void)in_sizes; (void)n_in; (void)out_size;
    const float* inputs = (const float*)d_in[0];
    const float* EC     = (const float*)d_in[1];
    const float* pos    = (const float*)d_in[2];
    const float* Wq     = (const float*)d_in[3];
    const float* Wk     = (const float*)d_in[4];
    const float* Wv     = (const float*)d_in[5];
    const float* lin_w  = (const float*)d_in[6];
    const float* lin_b  = (const float*)d_in[7];

    float* out = (float*)d_out;                 // [N, F]
    float* ST  = out + (size_t)NN * FF;         // [N, T, H*T]

    float *qp, *kp, *vp;
    cudaGetSymbolAddress((void**)&qp, g_q);
    cudaGetSymbolAddress((void**)&kp, g_k);
    cudaGetSymbolAddress((void**)&vp, g_v);

    const size_t smem_proj = (size_t)(BM * AS_STRIDE + BK * BS_STRIDE) * sizeof(float); // 35328
    const size_t smem_ff   = (size_t)(BM * BS_STRIDE) * sizeof(float);                  // 67584 (Ys aliases)
    const size_t smem_gemm_max = smem_ff > smem_proj ? smem_ff : smem_proj;
    const size_t smem_attn = (size_t)(3 * 16 * QS) * sizeof(float);                     // 49920

    cudaFuncSetAttribute(gemm_k, cudaFuncAttributeMaxDynamicSharedMemorySize, (int)smem_gemm_max);
    cudaFuncSetAttribute(attn_k, cudaFuncAttributeMaxDynamicSharedMemorySize, (int)smem_attn);

    dim3 grid(FF / BN, MM / BM);   // (2, 4096)

    // q = (inputs+pos) @ Wq ; k = EC @ Wk ; v = (inputs+pos) @ Wv
    gemm_k<<<grid, 256, smem_proj>>>(inputs, pos, 1, Wq, 0, qp, 0, nullptr, nullptr, nullptr, nullptr);
    gemm_k<<<grid, 256, smem_proj>>>(EC,     pos, 0, Wk, 0, kp, 0, nullptr, nullptr, nullptr, nullptr);
    gemm_k<<<grid, 256, smem_proj>>>(inputs, pos, 1, Wv, 0, vp, 0, nullptr, nullptr, nullptr, nullptr);

    // attention + softmax + ST + ctx (ctx overwrites g_q)
    attn_k<<<NN, 256, smem_attn>>>(ST);

    // ff = relu(ctx @ lin_w.T + b) + ctx + temporal; out = mean over T
    gemm_k<<<grid, 256, smem_ff>>>(qp, pos, 0, lin_w, 1, nullptr, 1, qp, inputs, lin_b, out);
}

// round 12
// speedup vs baseline: 2.0579x; 2.0579x over previous
#include <cuda_runtime.h>
#include <cuda_fp16.h>
#include <cstdint>

#define NNODES 32768
#define FF 256
#define AHS 264      // half-buffer row stride (halfs)
#define KFS 260      // f32-buffer row stride (floats)

// Pre-transposed half weights, layout [k][n]: 0=Wq 1=Wk 2=Wv 3=lin_w^T
__device__ __half g_wt[4][65536];

__global__ void prep_w(const float* __restrict__ Wq, const float* __restrict__ Wk,
                       const float* __restrict__ Wv, const float* __restrict__ lw) {
    int idx = blockIdx.x * 256 + threadIdx.x;   // idx = k*256 + n
    int k = idx >> 8, n = idx & 255;
    g_wt[0][idx] = __float2half(Wq[idx]);
    g_wt[1][idx] = __float2half(Wk[idx]);
    g_wt[2][idx] = __float2half(Wv[idx]);
    g_wt[3][idx] = __float2half(lw[n * 256 + k]);   // transpose [out,in] -> [k][n]
}

__device__ __forceinline__ uint32_t smem_u32(const void* p) {
    uint32_t a;
    asm("{.reg .u64 t; cvta.to.shared.u64 t, %1; cvt.u32.u64 %0, t;}" : "=r"(a) : "l"(p));
    return a;
}
__device__ __forceinline__ void ldsm4(uint32_t a, uint32_t* r) {
    asm volatile("ldmatrix.sync.aligned.m8n8.x4.shared.b16 {%0,%1,%2,%3},[%4];"
                 : "=r"(r[0]), "=r"(r[1]), "=r"(r[2]), "=r"(r[3]) : "r"(a));
}
__device__ __forceinline__ void ldsm4t(uint32_t a, uint32_t* r) {
    asm volatile("ldmatrix.sync.aligned.m8n8.x4.trans.shared.b16 {%0,%1,%2,%3},[%4];"
                 : "=r"(r[0]), "=r"(r[1]), "=r"(r[2]), "=r"(r[3]) : "r"(a));
}
__device__ __forceinline__ void hmma(float* c, const uint32_t* a, const uint32_t* b) {
    asm volatile("mma.sync.aligned.m16n8k16.row.col.f32.f16.f16.f32 "
                 "{%0,%1,%2,%3},{%4,%5,%6,%7},{%8,%9},{%0,%1,%2,%3};"
                 : "+f"(c[0]), "+f"(c[1]), "+f"(c[2]), "+f"(c[3])
                 : "r"(a[0]), "r"(a[1]), "r"(a[2]), "r"(a[3]), "r"(b[0]), "r"(b[1]));
}
__device__ __forceinline__ void cpasync16(uint32_t dst, const void* src) {
    asm volatile("cp.async.ca.shared.global [%0],[%1],16;" :: "r"(dst), "l"(src) : "memory");
}

// 64x256 @ 256x256 GEMM core: A half in smem (stride AHS), W half global [k][n],
// weight chunks (32x256 = 16KB) double-buffered via cp.async.
// Warp tile 32m x 64n (8 warps: 2M x 4N). Result in acc (fp32).
__device__ __forceinline__ void gemm_core(uint32_t sAh, uint32_t sBs,
                                          const __half* __restrict__ Wg,
                                          float acc[2][8][4], int tid) {
    const int lane = tid & 31, warp = tid >> 5;
    const int m0w = (warp >> 2) * 32, n0w = (warp & 3) * 64;
#pragma unroll
    for (int mt = 0; mt < 2; mt++)
#pragma unroll
        for (int nt = 0; nt < 8; nt++)
#pragma unroll
            for (int e = 0; e < 4; e++) acc[mt][nt][e] = 0.f;

    const uint32_t aBase = sAh + (uint32_t)(((m0w + (lane & 15)) * AHS) + ((lane >> 4) * 8)) * 2;
    const uint32_t bLane = (uint32_t)(((lane & 15) * AHS) + n0w + ((lane >> 4) * 8)) * 2;

    // prefetch chunk 0 -> buf 0
#pragma unroll
    for (int i = 0; i < 4; i++) {
        int idx = tid + i * 256;
        int k = idx >> 5, nb = (idx & 31) * 8;
        cpasync16(sBs + (uint32_t)(k * AHS + nb) * 2, Wg + k * 256 + nb);
    }
    asm volatile("cp.async.commit_group;" ::: "memory");

    for (int c = 0; c < 8; c++) {
        const uint32_t bufOff = (uint32_t)(c & 1) * 32 * AHS * 2;
        if (c < 7) {
            const uint32_t nbuf = (uint32_t)((c + 1) & 1) * 32 * AHS * 2;
#pragma unroll
            for (int i = 0; i < 4; i++) {
                int idx = tid + i * 256;
                int k = idx >> 5, nb = (idx & 31) * 8;
                cpasync16(sBs + nbuf + (uint32_t)(k * AHS + nb) * 2,
                          Wg + (c + 1) * 32 * 256 + k * 256 + nb);
            }
            asm volatile("cp.async.commit_group;" ::: "memory");
            asm volatile("cp.async.wait_group 1;" ::: "memory");
        } else {
            asm volatile("cp.async.wait_group 0;" ::: "memory");
        }
        __syncthreads();
#pragma unroll
        for (int kk = 0; kk < 2; kk++) {
            uint32_t a[2][4], b[8][2];
#pragma unroll
            for (int mt = 0; mt < 2; mt++)
                ldsm4(aBase + (uint32_t)(mt * 16 * AHS + c * 32 + kk * 16) * 2, a[mt]);
#pragma unroll
            for (int nt4 = 0; nt4 < 4; nt4++) {
                uint32_t r[4];
                ldsm4t(sBs + bufOff + bLane + (uint32_t)(kk * 16 * AHS + nt4 * 16) * 2, r);
                b[nt4 * 2][0] = r[0]; b[nt4 * 2][1] = r[1];
                b[nt4 * 2 + 1][0] = r[2]; b[nt4 * 2 + 1][1] = r[3];
            }
#pragma unroll
            for (int mt = 0; mt < 2; mt++)
#pragma unroll
                for (int nt = 0; nt < 8; nt++)
                    hmma(acc[mt][nt], a[mt], b[nt]);
        }
        __syncthreads();
    }
}

__device__ __forceinline__ void store_half(__half* D, float acc[2][8][4], int tid) {
    const int lane = tid & 31, warp = tid >> 5;
    const int m0w = (warp >> 2) * 32, n0w = (warp & 3) * 64;
#pragma unroll
    for (int mt = 0; mt < 2; mt++)
#pragma unroll
        for (int nt = 0; nt < 8; nt++) {
            int r = m0w + mt * 16 + (lane >> 2);
            int c = n0w + nt * 8 + (lane & 3) * 2;
            *(__half2*)(D + r * AHS + c) = __floats2half2_rn(acc[mt][nt][0], acc[mt][nt][1]);
            *(__half2*)(D + (r + 8) * AHS + c) = __floats2half2_rn(acc[mt][nt][2], acc[mt][nt][3]);
        }
}

// smem layout (bytes):
#define SO_BIAS 0
#define SO_AH   1024
#define SO_QH   34816
#define SO_VH   68608
#define SO_KF   102400
#define SO_BS   168960
#define SMEM_TOTAL 202752

__global__ void __launch_bounds__(256, 1)
fused_k(const float* __restrict__ inputs, const float* __restrict__ EC,
        const float* __restrict__ pos, const float* __restrict__ lin_b,
        float* __restrict__ out, float* __restrict__ ST) {
    extern __shared__ char sh[];
    float*  sBias = (float*)(sh + SO_BIAS);
    __half* Ah = (__half*)(sh + SO_AH);   // EC -> temporal (persists to epilogue)
    __half* Qh = (__half*)(sh + SO_QH);   // q (half)
    __half* Vh = (__half*)(sh + SO_VH);   // v -> ctx-half
    float*  Kf = (float*)(sh + SO_KF);    // k fp32 -> ctx fp32
    __half* Bs = (__half*)(sh + SO_BS);   // weight double buffer

    const int tid = threadIdx.x;
    const int cta = blockIdx.x;
    const size_t rowG0 = (size_t)cta * 64;

    const uint32_t sAh = smem_u32(Ah), sBs = smem_u32(Bs);
    sBias[tid] = lin_b[tid];

    // ---- stage EC -> Ah ----
#pragma unroll
    for (int i = 0; i < 16; i++) {
        int idx = tid + i * 256;
        int r = idx >> 6, c = (idx & 63) * 4;
        float4 t = *(const float4*)(EC + (rowG0 + r) * FF + c);
        __half2* d = (__half2*)(Ah + r * AHS + c);
        d[0] = __floats2half2_rn(t.x, t.y);
        d[1] = __floats2half2_rn(t.z, t.w);
    }
    float acc[2][8][4];

    // ---- K = EC @ Wk -> Kf (fp32) ----
    gemm_core(sAh, sBs, g_wt[1], acc, tid);
    {
        const int lane = tid & 31, warp = tid >> 5;
        const int m0w = (warp >> 2) * 32, n0w = (warp & 3) * 64;
#pragma unroll
        for (int mt = 0; mt < 2; mt++)
#pragma unroll
            for (int nt = 0; nt < 8; nt++) {
                int r = m0w + mt * 16 + (lane >> 2);
                int c = n0w + nt * 8 + (lane & 3) * 2;
                *(float2*)(Kf + r * KFS + c) = make_float2(acc[mt][nt][0], acc[mt][nt][1]);
                *(float2*)(Kf + (r + 8) * KFS + c) = make_float2(acc[mt][nt][2], acc[mt][nt][3]);
            }
    }
    __syncthreads();

    // ---- stage temporal = inputs + pos -> Ah ----
#pragma unroll
    for (int i = 0; i < 16; i++) {
        int idx = tid + i * 256;
        int r = idx >> 6, c = (idx & 63) * 4;
        float4 t = *(const float4*)(inputs + (rowG0 + r) * FF + c);
        float4 p = *(const float4*)(pos + (r & 15) * FF + c);
        t.x += p.x; t.y += p.y; t.z += p.z; t.w += p.w;
        __half2* d = (__half2*)(Ah + r * AHS + c);
        d[0] = __floats2half2_rn(t.x, t.y);
        d[1] = __floats2half2_rn(t.z, t.w);
    }
    // ---- Q = temporal @ Wq -> Qh ----
    gemm_core(sAh, sBs, g_wt[0], acc, tid);
    store_half(Qh, acc, tid);
    // ---- V = temporal @ Wv -> Vh ----
    gemm_core(sAh, sBs, g_wt[2], acc, tid);
    store_half(Vh, acc, tid);
    __syncthreads();

    // ---- attention: thread owns (i64, h) pairs; probs kept in regs ----
    const int i64 = tid & 63;
    const int node = i64 >> 4;
    const int hbase = tid >> 6;
    float pr[4][16];
#pragma unroll
    for (int p = 0; p < 4; p++) {
        const int h = (hbase + p * 4) & 15;
        float qf[16];
        const __half2* q2 = (const __half2*)(Qh + i64 * AHS + h * 16);
#pragma unroll
        for (int e = 0; e < 8; e++) {
            float2 t = __half22float2(q2[e]);
            qf[2 * e] = t.x; qf[2 * e + 1] = t.y;
        }
        float sc[16], mx = -1e30f;
#pragma unroll
        for (int j = 0; j < 16; j++) {
            const float* kr = Kf + (node * 16 + j) * KFS + h * 16;
            float s = 0.f;
#pragma unroll
            for (int d = 0; d < 16; d++) s += qf[d] * kr[d];
            s *= 0.25f;
            sc[j] = s; mx = fmaxf(mx, s);
        }
        float sum = 0.f;
#pragma unroll
        for (int j = 0; j < 16; j++) { sc[j] = __expf(sc[j] - mx); sum += sc[j]; }
        const float inv = 1.f / sum;
#pragma unroll
        for (int j = 0; j < 16; j++) pr[p][j] = sc[j] * inv;
        float* stp = ST + (rowG0 + i64) * FF + h * 16;
#pragma unroll
        for (int j0 = 0; j0 < 16; j0 += 4)
            *(float4*)(stp + j0) = make_float4(pr[p][j0], pr[p][j0 + 1], pr[p][j0 + 2], pr[p][j0 + 3]);
    }
    __syncthreads();   // all Kf reads (scores) done before ctx overwrites Kf

    // ---- ctx = P @ V -> Kf (fp32) ----
#pragma unroll
    for (int p = 0; p < 4; p++) {
        const int h = (hbase + p * 4) & 15;
        float ct[16];
#pragma unroll
        for (int d = 0; d < 16; d++) ct[d] = 0.f;
#pragma unroll
        for (int j = 0; j < 16; j++) {
            const float pj = pr[p][j];
            const __half2* vr = (const __half2*)(Vh + (node * 16 + j) * AHS + h * 16);
#pragma unroll
            for (int e = 0; e < 8; e++) {
                float2 tv = __half22float2(vr[e]);
                ct[2 * e]     += pj * tv.x;
                ct[2 * e + 1] += pj * tv.y;
            }
        }
        float* cd = Kf + i64 * KFS + h * 16;
#pragma unroll
        for (int d0 = 0; d0 < 16; d0 += 4)
            *(float4*)(cd + d0) = make_float4(ct[d0], ct[d0 + 1], ct[d0 + 2], ct[d0 + 3]);
    }
    __syncthreads();   // Vh reads done -> safe to overwrite with ctx-half

    // ---- ctx fp32 -> Vh half (ff A operand) ----
#pragma unroll
    for (int i = 0; i < 32; i++) {
        int idx = tid + i * 256;          // half2 index, 8192 total
        int r = idx >> 7, c2 = (idx & 127) * 2;
        float2 t = *(const float2*)(Kf + r * KFS + c2);
        *(__half2*)(Vh + r * AHS + c2) = __floats2half2_rn(t.x, t.y);
    }
    __syncthreads();

    // ---- FF GEMM: relu(ctx @ lin_w^T + b) + ctx + temporal, mean over T ----
    gemm_core(smem_u32(Vh), sBs, g_wt[3], acc, tid);
    {
        const int lane = tid & 31, warp = tid >> 5;
        const int m0w = (warp >> 2) * 32, n0w = (warp & 3) * 64;
#pragma unroll
        for (int mt = 0; mt < 2; mt++) {
            const int nodeg = cta * 4 + (warp >> 2) * 2 + mt;
#pragma unroll
            for (int nt = 0; nt < 8; nt++) {
                const int r1 = m0w + mt * 16 + (lane >> 2);
                const int r2 = r1 + 8;
                const int c0 = n0w + nt * 8 + (lane & 3) * 2;
                const float b0 = sBias[c0], b1 = sBias[c0 + 1];
                float y00 = fmaxf(acc[mt][nt][0] + b0, 0.f) + Kf[r1 * KFS + c0]     + __half2float(Ah[r1 * AHS + c0]);
                float y01 = fmaxf(acc[mt][nt][1] + b1, 0.f) + Kf[r1 * KFS + c0 + 1] + __half2float(Ah[r1 * AHS + c0 + 1]);
                float y10 = fmaxf(acc[mt][nt][2] + b0, 0.f) + Kf[r2 * KFS + c0]     + __half2float(Ah[r2 * AHS + c0]);
                float y11 = fmaxf(acc[mt][nt][3] + b1, 0.f) + Kf[r2 * KFS + c0 + 1] + __half2float(Ah[r2 * AHS + c0 + 1]);
                float s0 = y00 + y10, s1 = y01 + y11;
#pragma unroll
                for (int off = 16; off >= 4; off >>= 1) {
                    s0 += __shfl_xor_sync(0xffffffffu, s0, off);
                    s1 += __shfl_xor_sync(0xffffffffu, s1, off);
                }
                if ((lane >> 2) == 0) {
                    out[(size_t)nodeg * FF + c0]     = s0 * (1.f / 16.f);
                    out[(size_t)nodeg * FF + c0 + 1] = s1 * (1.f / 16.f);
                }
            }
        }
    }
}

extern "C" void kernel_launch(void* const* d_in, const int* in_sizes, int n_in,
                              void* d_out, int out_size) {
    (void)in_sizes; (void)n_in; (void)out_size;
    const float* inputs = (const float*)d_in[0];
    const float* EC     = (const float*)d_in[1];
    const float* pos    = (const float*)d_in[2];
    const float* Wq     = (const float*)d_in[3];
    const float* Wk     = (const float*)d_in[4];
    const float* Wv     = (const float*)d_in[5];
    const float* lin_w  = (const float*)d_in[6];
    const float* lin_b  = (const float*)d_in[7];

    float* out = (float*)d_out;                       // [N, F]
    float* ST  = out + (size_t)NNODES * FF;           // [N, T, H*T]

    cudaFuncSetAttribute(fused_k, cudaFuncAttributeMaxDynamicSharedMemorySize, SMEM_TOTAL);

    prep_w<<<256, 256>>>(Wq, Wk, Wv, lin_w);
    fused_k<<<NNODES / 4, 256, SMEM_TOTAL>>>(inputs, EC, pos, lin_b, out, ST);
}